// round 1
// baseline (speedup 1.0000x reference)
#include <cuda_runtime.h>
#include <cuda_bf16.h>
#include <cstdint>

#define NN 50000
#define EE 100000
#define CC 256
#define NW_WORDS 1568   // ceil(50000/32)=1563, padded

// ---------------- scratch (static device globals; no allocation) -------------
__device__ float g_xt[NN * CC];        // 51.2 MB  : xt = x @ W^T + b
__device__ float g_Wt[CC * CC];        // W transposed: Wt[k*C + j] = W[j*C + k]
__device__ int   g_deg[NN];
__device__ int   g_off[NN + 1];
__device__ int   g_cur[NN];
__device__ int   g_srclist[EE];
__device__ int   g_mask[NN];

// ---------------- prep: transpose W ------------------------------------------
__global__ void prep_kernel(const float* __restrict__ W) {
    int j = blockIdx.x;          // 256 blocks
    int k = threadIdx.x;         // 256 threads
    g_Wt[k * CC + j] = W[j * CC + k];
}

__global__ void zero_kernel() {
    int i = blockIdx.x * blockDim.x + threadIdx.x;
    if (i < NN) g_deg[i] = 0;
}

// ---------------- GEMM: xt = x @ W^T + b  (fp32, 128x128 tile, 8x8/thread) ---
__global__ __launch_bounds__(256, 2)
void gemm_kernel(const float* __restrict__ x, const float* __restrict__ b, int M) {
    __shared__ float As[8][128];
    __shared__ float Bs[8][128];

    const int tid = threadIdx.x;
    const int m0 = blockIdx.y * 128;
    const int n0 = blockIdx.x * 128;

    const int tr = tid / 16;     // 0..15 row group
    const int tc = tid % 16;     // 0..15 col group

    // A loads: 128 rows x 8 k per tile -> each thread one float4
    const int arow = tid >> 1;
    const int acol = (tid & 1) * 4;
    // B loads: 8 k x 128 n -> each thread one float4
    const int brow = tid >> 5;
    const int bcol = (tid & 31) * 4;

    float acc[8][8];
#pragma unroll
    for (int i = 0; i < 8; i++)
#pragma unroll
        for (int j = 0; j < 8; j++) acc[i][j] = 0.f;

    const int arow_g = m0 + arow;
    for (int k0 = 0; k0 < CC; k0 += 8) {
        float4 av = make_float4(0.f, 0.f, 0.f, 0.f);
        if (arow_g < M)
            av = *reinterpret_cast<const float4*>(x + (size_t)arow_g * CC + k0 + acol);
        As[acol + 0][arow] = av.x;
        As[acol + 1][arow] = av.y;
        As[acol + 2][arow] = av.z;
        As[acol + 3][arow] = av.w;

        float4 bv = *reinterpret_cast<const float4*>(g_Wt + (size_t)(k0 + brow) * CC + n0 + bcol);
        *reinterpret_cast<float4*>(&Bs[brow][bcol]) = bv;
        __syncthreads();

#pragma unroll
        for (int kk = 0; kk < 8; kk++) {
            float4 a0 = *reinterpret_cast<float4*>(&As[kk][tr * 8]);
            float4 a1 = *reinterpret_cast<float4*>(&As[kk][tr * 8 + 4]);
            float4 b0 = *reinterpret_cast<float4*>(&Bs[kk][tc * 8]);
            float4 b1 = *reinterpret_cast<float4*>(&Bs[kk][tc * 8 + 4]);
            float ar[8] = {a0.x, a0.y, a0.z, a0.w, a1.x, a1.y, a1.z, a1.w};
            float br[8] = {b0.x, b0.y, b0.z, b0.w, b1.x, b1.y, b1.z, b1.w};
#pragma unroll
            for (int i = 0; i < 8; i++)
#pragma unroll
                for (int j = 0; j < 8; j++) acc[i][j] += ar[i] * br[j];
        }
        __syncthreads();
    }

    float bias[8];
#pragma unroll
    for (int j = 0; j < 8; j++) bias[j] = b[n0 + tc * 8 + j];

#pragma unroll
    for (int i = 0; i < 8; i++) {
        int row = m0 + tr * 8 + i;
        if (row < M) {
            float v[8];
#pragma unroll
            for (int j = 0; j < 8; j++) v[j] = acc[i][j] + bias[j];
            float* dst = g_xt + (size_t)row * CC + n0 + tc * 8;
            *reinterpret_cast<float4*>(dst)     = make_float4(v[0], v[1], v[2], v[3]);
            *reinterpret_cast<float4*>(dst + 4) = make_float4(v[4], v[5], v[6], v[7]);
        }
    }
}

// ---------------- degree count -----------------------------------------------
__global__ void deg_kernel(const int* __restrict__ ei) {
    int e = blockIdx.x * blockDim.x + threadIdx.x;
    if (e < EE) {
        int dst = ei[EE + e];
        atomicAdd(&g_deg[dst], 1);
    }
}

// ---------------- exclusive scan (single block, 1024 threads) ----------------
__global__ __launch_bounds__(1024, 1)
void scan_kernel() {
    __shared__ int wsums[32];
    const int tid = threadIdx.x;
    const int PER = 49;  // 1024*49 = 50176 >= 50000
    const int start = tid * PER;

    int s = 0;
    for (int i = 0; i < PER; i++) {
        int idx = start + i;
        if (idx < NN) s += g_deg[idx];
    }
    int lane = tid & 31, wid = tid >> 5;
    int v = s;
#pragma unroll
    for (int o = 1; o < 32; o <<= 1) {
        int n = __shfl_up_sync(0xFFFFFFFFu, v, o);
        if (lane >= o) v += n;
    }
    if (lane == 31) wsums[wid] = v;
    __syncthreads();
    if (wid == 0) {
        int w = wsums[lane];
#pragma unroll
        for (int o = 1; o < 32; o <<= 1) {
            int n = __shfl_up_sync(0xFFFFFFFFu, w, o);
            if (lane >= o) w += n;
        }
        wsums[lane] = w;
    }
    __syncthreads();
    int excl = v - s + (wid > 0 ? wsums[wid - 1] : 0);
    int off = excl;
    for (int i = 0; i < PER; i++) {
        int idx = start + i;
        if (idx < NN) {
            int d = g_deg[idx];
            g_off[idx] = off;
            g_cur[idx] = off;
            off += d;
        }
    }
    if (tid == 1023) g_off[NN] = off;
}

// ---------------- CSR fill ---------------------------------------------------
__global__ void fill_kernel(const int* __restrict__ ei) {
    int e = blockIdx.x * blockDim.x + threadIdx.x;
    if (e < EE) {
        int dst = ei[EE + e];
        int p = atomicAdd(&g_cur[dst], 1);
        g_srclist[p] = ei[e];
    }
}

// ---------------- sequential greedy merge (1 block, warp-windowed) -----------
// fired(i) <=> s!=t && disc0[t] && no fired j<i with (s_j==s_i || s_j==t_i || t_j==t_i)
__global__ __launch_bounds__(256, 1)
void merge_kernel(const int* __restrict__ ei) {
    __shared__ unsigned rem_bits[NW_WORDS];
    __shared__ unsigned disc_bits[NW_WORDS];
    const int tid = threadIdx.x;

    for (int i = tid; i < NW_WORDS; i += blockDim.x) {
        rem_bits[i] = 0xFFFFFFFFu;
        disc_bits[i] = 0u;
    }
    __syncthreads();
    // disc0[v] = 1 iff v appears as a source
    for (int e = tid; e < EE; e += blockDim.x) {
        int s = ei[e];
        atomicOr(&disc_bits[s >> 5], 1u << (s & 31));
    }
    __syncthreads();

    if (tid < 32) {
        const unsigned FULL = 0xFFFFFFFFu;
        const int lane = tid;
        const unsigned lt = (lane == 0) ? 0u : ((1u << lane) - 1u);

        for (int base = 0; base < EE; base += 32) {
            int i = base + lane;
            int s = -1, t = -2;
            bool valid = (i < EE);
            if (valid) { s = ei[i]; t = ei[EE + i]; }

            bool cond0 = false;
            if (valid && s != t) {
                unsigned rs = (rem_bits[s >> 5] >> (s & 31)) & 1u;
                unsigned rt = (rem_bits[t >> 5] >> (t & 31)) & 1u;
                unsigned dt = (disc_bits[t >> 5] >> (t & 31)) & 1u;
                cond0 = rs && rt && dt;
            }

            unsigned cand = __ballot_sync(FULL, cond0);
            unsigned fired = 0;
            if (cand) {
                // conflict mask: candidate lanes j that would block me if fired
                unsigned conflict = 0;
                unsigned it = cand;
                while (it) {
                    int j = __ffs(it) - 1;
                    it &= it - 1;
                    int sj = __shfl_sync(FULL, s, j);
                    int tj = __shfl_sync(FULL, t, j);
                    if (sj == s || sj == t || tj == t) conflict |= (1u << j);
                }
                conflict &= lt & cand;

                // in-warp DAG fixpoint (dependencies go only to lower lanes)
                unsigned decided = ~cand;
                while (decided != FULL) {
                    bool undec = !((decided >> lane) & 1u);
                    bool ready = undec && ((conflict & ~decided) == 0u);
                    bool f = ready && ((conflict & fired) == 0u);
                    decided |= __ballot_sync(FULL, ready);
                    fired   |= __ballot_sync(FULL, f);
                }
                if ((fired >> lane) & 1u) {
                    atomicAnd(&rem_bits[s >> 5],  ~(1u << (s & 31)));
                    atomicAnd(&disc_bits[t >> 5], ~(1u << (t & 31)));
                }
            }
            __syncwarp(FULL);
        }
    }
    __syncthreads();
    for (int v = tid; v < NN; v += blockDim.x)
        g_mask[v] = (rem_bits[v >> 5] >> (v & 31)) & 1;
}

// ---------------- gather-mean + mask + output (1 warp per node) --------------
__global__ __launch_bounds__(256, 8)
void out_kernel(float* __restrict__ out) {
    int warp = (blockIdx.x * blockDim.x + threadIdx.x) >> 5;
    int lane = threadIdx.x & 31;
    if (warp >= NN) return;
    const int v = warp;

    float4* o = reinterpret_cast<float4*>(out + (size_t)v * CC);
    if (!g_mask[v]) {
        o[lane]      = make_float4(0.f, 0.f, 0.f, 0.f);
        o[lane + 32] = make_float4(0.f, 0.f, 0.f, 0.f);
        return;
    }
    const float4* xv = reinterpret_cast<const float4*>(g_xt + (size_t)v * CC);
    float4 a0 = xv[lane];
    float4 a1 = xv[lane + 32];
    int s0 = g_off[v], s1 = g_off[v + 1];
    for (int j = s0; j < s1; j++) {
        int u = g_srclist[j];
        const float4* p = reinterpret_cast<const float4*>(g_xt + (size_t)u * CC);
        float4 q0 = p[lane];
        float4 q1 = p[lane + 32];
        a0.x += q0.x; a0.y += q0.y; a0.z += q0.z; a0.w += q0.w;
        a1.x += q1.x; a1.y += q1.y; a1.z += q1.z; a1.w += q1.w;
    }
    float inv = 1.f / (float)(s1 - s0 + 1);
    a0.x *= inv; a0.y *= inv; a0.z *= inv; a0.w *= inv;
    a1.x *= inv; a1.y *= inv; a1.z *= inv; a1.w *= inv;
    o[lane]      = a0;
    o[lane + 32] = a1;
}

// ---------------- tail: write mask (as float) + zero any padding -------------
__global__ void tail_kernel(float* __restrict__ out, int out_size) {
    int i = blockIdx.x * blockDim.x + threadIdx.x;
    int idx = NN * CC + i;
    if (idx < out_size)
        out[idx] = (i < NN) ? (float)g_mask[i] : 0.f;
}

// ---------------- launch -----------------------------------------------------
extern "C" void kernel_launch(void* const* d_in, const int* in_sizes, int n_in,
                              void* d_out, int out_size) {
    const float* x  = (const float*)d_in[0];
    const int*   ei = (const int*)d_in[1];
    const float* W  = (const float*)d_in[2];
    const float* b  = (const float*)d_in[3];
    float* out = (float*)d_out;

    const int M = in_sizes[0] / CC;   // 50000

    prep_kernel<<<CC, CC>>>(W);
    zero_kernel<<<(NN + 255) / 256, 256>>>();
    gemm_kernel<<<dim3(2, (M + 127) / 128), 256>>>(x, b, M);
    deg_kernel<<<(EE + 255) / 256, 256>>>(ei);
    scan_kernel<<<1, 1024>>>();
    fill_kernel<<<(EE + 255) / 256, 256>>>(ei);
    merge_kernel<<<1, 256>>>(ei);
    out_kernel<<<(NN * 32 + 255) / 256, 256>>>(out);

    int tail = out_size - NN * CC;
    if (tail > 0)
        tail_kernel<<<(tail + 255) / 256, 256>>>(out, out_size);
}

// round 2
// speedup vs baseline: 5.9431x; 5.9431x over previous
#include <cuda_runtime.h>
#include <cuda_bf16.h>
#include <cstdint>

#define NN 50000
#define EE 100000
#define CC 256
#define NW_WORDS 1568          // ceil(50000/32) node bitmap words (padded)
#define EW_WORDS 3125          // ceil(100000/32) edge bitmap words
#define INF_I 0x7FFFFFFF
#define IDXM 131071            // 2^17-1, EE < 2^17
#define ROUNDS 7

// ---------------- scratch (static device globals; no allocation) -------------
__device__ float g_xt[NN * CC];        // xt = x @ W^T + b
__device__ float g_Wt[CC * CC];
__device__ int   g_deg[NN];
__device__ int   g_off[NN + 1];
__device__ int   g_cur[NN];
__device__ int   g_srclist[EE];
__device__ int   g_mask[NN];

// merge state
__device__ int      g_minFS[NN];       // min index of fired edge with source v
__device__ int      g_minFT[NN];       // min index of fired edge with target v
__device__ int      g_mUS[NN];         // stamped atomicMax key: undecided min-src
__device__ int      g_mUT[NN];         // stamped atomicMax key: undecided min-tgt
__device__ unsigned g_disc0[NW_WORDS]; // v appears as a source
__device__ unsigned g_und[EW_WORDS];   // undecided edge bitmap
__device__ int      g_wl[2][EE];       // worklist ping-pong
__device__ int      g_cnt[2];

// ---------------- init: reset ALL persistent state every call ----------------
__global__ void init_kernel() {
    int i = blockIdx.x * blockDim.x + threadIdx.x;
    if (i < NN) {
        g_minFS[i] = INF_I;
        g_minFT[i] = INF_I;
        g_mUS[i] = 0;
        g_mUT[i] = 0;
        g_deg[i] = 0;
    }
    if (i < NW_WORDS) g_disc0[i] = 0u;
    if (i < EW_WORDS) g_und[i] = 0u;
    if (i == 0) { g_cnt[0] = 0; g_cnt[1] = 0; }
}

// ---------------- prep: transpose W ------------------------------------------
__global__ void prep_kernel(const float* __restrict__ W) {
    int j = blockIdx.x;
    int k = threadIdx.x;
    g_Wt[k * CC + j] = W[j * CC + k];
}

// ---------------- GEMM: xt = x @ W^T + b  (fp32, 128x128 tile, 8x8/thread) ---
__global__ __launch_bounds__(256, 2)
void gemm_kernel(const float* __restrict__ x, const float* __restrict__ b, int M) {
    __shared__ float As[8][128];
    __shared__ float Bs[8][128];

    const int tid = threadIdx.x;
    const int m0 = blockIdx.y * 128;
    const int n0 = blockIdx.x * 128;
    const int tr = tid / 16;
    const int tc = tid % 16;
    const int arow = tid >> 1;
    const int acol = (tid & 1) * 4;
    const int brow = tid >> 5;
    const int bcol = (tid & 31) * 4;

    float acc[8][8];
#pragma unroll
    for (int i = 0; i < 8; i++)
#pragma unroll
        for (int j = 0; j < 8; j++) acc[i][j] = 0.f;

    const int arow_g = m0 + arow;
    for (int k0 = 0; k0 < CC; k0 += 8) {
        float4 av = make_float4(0.f, 0.f, 0.f, 0.f);
        if (arow_g < M)
            av = *reinterpret_cast<const float4*>(x + (size_t)arow_g * CC + k0 + acol);
        As[acol + 0][arow] = av.x;
        As[acol + 1][arow] = av.y;
        As[acol + 2][arow] = av.z;
        As[acol + 3][arow] = av.w;

        float4 bv = *reinterpret_cast<const float4*>(g_Wt + (size_t)(k0 + brow) * CC + n0 + bcol);
        *reinterpret_cast<float4*>(&Bs[brow][bcol]) = bv;
        __syncthreads();

#pragma unroll
        for (int kk = 0; kk < 8; kk++) {
            float4 a0 = *reinterpret_cast<float4*>(&As[kk][tr * 8]);
            float4 a1 = *reinterpret_cast<float4*>(&As[kk][tr * 8 + 4]);
            float4 b0 = *reinterpret_cast<float4*>(&Bs[kk][tc * 8]);
            float4 b1 = *reinterpret_cast<float4*>(&Bs[kk][tc * 8 + 4]);
            float ar[8] = {a0.x, a0.y, a0.z, a0.w, a1.x, a1.y, a1.z, a1.w};
            float br[8] = {b0.x, b0.y, b0.z, b0.w, b1.x, b1.y, b1.z, b1.w};
#pragma unroll
            for (int i = 0; i < 8; i++)
#pragma unroll
                for (int j = 0; j < 8; j++) acc[i][j] += ar[i] * br[j];
        }
        __syncthreads();
    }

    float bias[8];
#pragma unroll
    for (int j = 0; j < 8; j++) bias[j] = b[n0 + tc * 8 + j];

#pragma unroll
    for (int i = 0; i < 8; i++) {
        int row = m0 + tr * 8 + i;
        if (row < M) {
            float v[8];
#pragma unroll
            for (int j = 0; j < 8; j++) v[j] = acc[i][j] + bias[j];
            float* dst = g_xt + (size_t)row * CC + n0 + tc * 8;
            *reinterpret_cast<float4*>(dst)     = make_float4(v[0], v[1], v[2], v[3]);
            *reinterpret_cast<float4*>(dst + 4) = make_float4(v[4], v[5], v[6], v[7]);
        }
    }
}

// ---------------- disc0 bitmap + degree count (fused) -------------------------
__global__ void disc_deg_kernel(const int* __restrict__ ei) {
    int e = blockIdx.x * blockDim.x + threadIdx.x;
    if (e < EE) {
        int s = ei[e];
        int t = ei[EE + e];
        atomicOr(&g_disc0[s >> 5], 1u << (s & 31));
        atomicAdd(&g_deg[t], 1);
    }
}

// ---------------- build initial worklist (static base filter) ----------------
__global__ void build_kernel(const int* __restrict__ ei) {
    int e = blockIdx.x * blockDim.x + threadIdx.x;
    if (e < EE) {
        int s = ei[e];
        int t = ei[EE + e];
        bool base = (s != t) && ((g_disc0[t >> 5] >> (t & 31)) & 1u);
        if (base) {
            int pos = atomicAdd(&g_cnt[0], 1);
            g_wl[0][pos] = e;
            atomicOr(&g_und[e >> 5], 1u << (e & 31));
        }
    }
}

// ---------------- round pass A: stamp per-node min undecided index -----------
__global__ void stampA_kernel(const int* __restrict__ ei, int round) {
    int cur = (round - 1) & 1, nxt = round & 1;
    if (blockIdx.x == 0 && threadIdx.x == 0) g_cnt[nxt] = 0;
    int n = g_cnt[cur];
    int idx = blockIdx.x * blockDim.x + threadIdx.x;
    if (idx >= n) return;
    int e = g_wl[cur][idx];
    int s = ei[e], t = ei[EE + e];
    int key = (round << 17) | (IDXM - e);
    atomicMax(&g_mUS[s], key);
    atomicMax(&g_mUT[t], key);
}

__device__ __forceinline__ int decode_stamp(int key, int round) {
    return ((key >> 17) == round) ? (IDXM - (key & IDXM)) : INF_I;
}

// ---------------- round pass B: decide fire/die/stay --------------------------
__global__ void decideB_kernel(const int* __restrict__ ei, int round) {
    int cur = (round - 1) & 1, nxt = round & 1;
    int n = g_cnt[cur];
    int idx = blockIdx.x * blockDim.x + threadIdx.x;
    if (idx >= n) return;
    int e = g_wl[cur][idx];
    int s = ei[e], t = ei[EE + e];

    bool killed = (g_minFS[s] < e) || (g_minFS[t] < e) || (g_minFT[t] < e);
    bool decided;
    if (!killed) {
        int a = decode_stamp(g_mUS[s], round);   // includes e itself
        int c = decode_stamp(g_mUS[t], round);
        int d = decode_stamp(g_mUT[t], round);   // includes e itself
        if (a >= e && c >= e && d >= e) {
            atomicMin(&g_minFS[s], e);
            atomicMin(&g_minFT[t], e);
            decided = true;
        } else {
            int pos = atomicAdd(&g_cnt[nxt], 1);
            g_wl[nxt][pos] = e;
            decided = false;
        }
    } else {
        decided = true;
    }
    if (decided) atomicAnd(&g_und[e >> 5], ~(1u << (e & 31)));
}

// ---------------- sequential finisher (1 warp, exact index order) ------------
__global__ __launch_bounds__(32, 1)
void finish_kernel(const int* __restrict__ ei) {
    __shared__ int sS[32];
    __shared__ int sT[32];
    const unsigned FULL = 0xFFFFFFFFu;
    const int lane = threadIdx.x;

    for (int w0 = 0; w0 < EW_WORDS; w0 += 32) {
        int w = w0 + lane;
        unsigned word = (w < EW_WORDS) ? __ldcg(&g_und[w]) : 0u;
        unsigned nz = __ballot_sync(FULL, word != 0u);
        while (nz) {
            int j = __ffs(nz) - 1;
            nz &= nz - 1;
            unsigned ww = __shfl_sync(FULL, word, j);
            int wi = w0 + j;
            int i = wi * 32 + lane;
            bool valid = ((ww >> lane) & 1u) != 0u;
            int s = 0, t = 0;
            if (valid) { s = __ldg(&ei[i]); t = __ldg(&ei[EE + i]); }
            bool cand = false;
            if (valid) {
                bool killed = (__ldcg(&g_minFS[s]) < i) ||
                              (__ldcg(&g_minFS[t]) < i) ||
                              (__ldcg(&g_minFT[t]) < i);
                cand = !killed;
            }
            sS[lane] = s;
            sT[lane] = t;
            __syncwarp(FULL);
            unsigned candm = __ballot_sync(FULL, cand);
            if (candm) {
                unsigned conflict = 0;
#pragma unroll
                for (int q = 0; q < 32; q++) {
                    if (q < lane && ((candm >> q) & 1u)) {
                        int sq = sS[q], tq = sT[q];
                        if (sq == s || sq == t || tq == t) conflict |= (1u << q);
                    }
                }
                unsigned fired = 0;
                unsigned decidedm = ~candm;
                while (decidedm != FULL) {
                    bool undec = !((decidedm >> lane) & 1u);
                    bool ready = undec && ((conflict & ~decidedm) == 0u);
                    bool f = ready && ((conflict & fired) == 0u);
                    decidedm |= __ballot_sync(FULL, ready);
                    fired    |= __ballot_sync(FULL, f);
                }
                if ((fired >> lane) & 1u) {
                    atomicMin(&g_minFS[s], i);
                    atomicMin(&g_minFT[t], i);
                }
                __threadfence();
            }
            __syncwarp(FULL);
        }
    }
}

// ---------------- mask: node kept iff never fired as a source ----------------
__global__ void mask_kernel() {
    int v = blockIdx.x * blockDim.x + threadIdx.x;
    if (v < NN) g_mask[v] = (g_minFS[v] == INF_I) ? 1 : 0;
}

// ---------------- exclusive scan (single block, 1024 threads) ----------------
__global__ __launch_bounds__(1024, 1)
void scan_kernel() {
    __shared__ int wsums[32];
    const int tid = threadIdx.x;
    const int PER = 49;
    const int start = tid * PER;

    int s = 0;
    for (int i = 0; i < PER; i++) {
        int idx = start + i;
        if (idx < NN) s += g_deg[idx];
    }
    int lane = tid & 31, wid = tid >> 5;
    int v = s;
#pragma unroll
    for (int o = 1; o < 32; o <<= 1) {
        int n = __shfl_up_sync(0xFFFFFFFFu, v, o);
        if (lane >= o) v += n;
    }
    if (lane == 31) wsums[wid] = v;
    __syncthreads();
    if (wid == 0) {
        int w = wsums[lane];
#pragma unroll
        for (int o = 1; o < 32; o <<= 1) {
            int n = __shfl_up_sync(0xFFFFFFFFu, w, o);
            if (lane >= o) w += n;
        }
        wsums[lane] = w;
    }
    __syncthreads();
    int excl = v - s + (wid > 0 ? wsums[wid - 1] : 0);
    int off = excl;
    for (int i = 0; i < PER; i++) {
        int idx = start + i;
        if (idx < NN) {
            int d = g_deg[idx];
            g_off[idx] = off;
            g_cur[idx] = off;
            off += d;
        }
    }
    if (tid == 1023) g_off[NN] = off;
}

// ---------------- CSR fill ---------------------------------------------------
__global__ void fill_kernel(const int* __restrict__ ei) {
    int e = blockIdx.x * blockDim.x + threadIdx.x;
    if (e < EE) {
        int dst = ei[EE + e];
        int p = atomicAdd(&g_cur[dst], 1);
        g_srclist[p] = ei[e];
    }
}

// ---------------- gather-mean + mask + output (1 warp per node) --------------
__global__ __launch_bounds__(256, 8)
void out_kernel(float* __restrict__ out) {
    int warp = (blockIdx.x * blockDim.x + threadIdx.x) >> 5;
    int lane = threadIdx.x & 31;
    if (warp >= NN) return;
    const int v = warp;

    float4* o = reinterpret_cast<float4*>(out + (size_t)v * CC);
    if (!g_mask[v]) {
        o[lane]      = make_float4(0.f, 0.f, 0.f, 0.f);
        o[lane + 32] = make_float4(0.f, 0.f, 0.f, 0.f);
        return;
    }
    const float4* xv = reinterpret_cast<const float4*>(g_xt + (size_t)v * CC);
    float4 a0 = xv[lane];
    float4 a1 = xv[lane + 32];
    int s0 = g_off[v], s1 = g_off[v + 1];
    for (int j = s0; j < s1; j++) {
        int u = g_srclist[j];
        const float4* p = reinterpret_cast<const float4*>(g_xt + (size_t)u * CC);
        float4 q0 = p[lane];
        float4 q1 = p[lane + 32];
        a0.x += q0.x; a0.y += q0.y; a0.z += q0.z; a0.w += q0.w;
        a1.x += q1.x; a1.y += q1.y; a1.z += q1.z; a1.w += q1.w;
    }
    float inv = 1.f / (float)(s1 - s0 + 1);
    a0.x *= inv; a0.y *= inv; a0.z *= inv; a0.w *= inv;
    a1.x *= inv; a1.y *= inv; a1.z *= inv; a1.w *= inv;
    o[lane]      = a0;
    o[lane + 32] = a1;
}

// ---------------- tail: write mask (as float) + zero any padding -------------
__global__ void tail_kernel(float* __restrict__ out, int out_size) {
    int i = blockIdx.x * blockDim.x + threadIdx.x;
    int idx = NN * CC + i;
    if (idx < out_size)
        out[idx] = (i < NN) ? (float)g_mask[i] : 0.f;
}

// ---------------- launch -----------------------------------------------------
extern "C" void kernel_launch(void* const* d_in, const int* in_sizes, int n_in,
                              void* d_out, int out_size) {
    const float* x  = (const float*)d_in[0];
    const int*   ei = (const int*)d_in[1];
    const float* W  = (const float*)d_in[2];
    const float* b  = (const float*)d_in[3];
    float* out = (float*)d_out;

    const int M = in_sizes[0] / CC;   // 50000

    init_kernel<<<(NN + 255) / 256, 256>>>();
    prep_kernel<<<CC, CC>>>(W);
    gemm_kernel<<<dim3(2, (M + 127) / 128), 256>>>(x, b, M);

    disc_deg_kernel<<<(EE + 255) / 256, 256>>>(ei);
    build_kernel<<<(EE + 255) / 256, 256>>>(ei);

    for (int r = 1; r <= ROUNDS; r++) {
        stampA_kernel<<<(EE + 255) / 256, 256>>>(ei, r);
        decideB_kernel<<<(EE + 255) / 256, 256>>>(ei, r);
    }
    finish_kernel<<<1, 32>>>(ei);
    mask_kernel<<<(NN + 255) / 256, 256>>>();

    scan_kernel<<<1, 1024>>>();
    fill_kernel<<<(EE + 255) / 256, 256>>>(ei);
    out_kernel<<<(NN * 32 + 255) / 256, 256>>>(out);

    int tail = out_size - NN * CC;
    if (tail > 0)
        tail_kernel<<<(tail + 255) / 256, 256>>>(out, out_size);
}